// round 16
// baseline (speedup 1.0000x reference)
#include <cuda_runtime.h>
#include <cstdint>
#include <cstddef>

#define NEGV -1e30f

constexpr int Bb = 32, Tt = 256, S = 258, Q = 20;
constexpr int CHS = 26;               // real steps per chunk
constexpr int WARM = 16;              // warm-up steps
constexpr int NKCH = 10;              // chunks per (dir,b)
constexpr int WIN = CHS + WARM;       // 42 (padded to 48 rows for mma)

// u vectors, transposed [s][v][b]
__device__ float g_uF[S * Q * Bb];
__device__ float g_uB[S * Q * Bb];

typedef unsigned long long ull;

// ---- helpers --------------------------------------------------------------
__device__ __forceinline__ ull pk2(float lo, float hi) {
    ull r;
    asm("mov.b64 %0, {%1, %2};" : "=l"(r) : "f"(lo), "f"(hi));
    return r;
}
__device__ __forceinline__ void upk2(float& lo, float& hi, ull v) {
    asm("mov.b64 {%0, %1}, %2;" : "=f"(lo), "=f"(hi) : "l"(v));
}
__device__ __forceinline__ void ffma2(ull& d, ull a, ull b) {
    asm("fma.rn.f32x2 %0, %1, %2, %0;" : "+l"(d) : "l"(a), "l"(b));
}
__device__ __forceinline__ void fadd2(ull& d, ull a) {
    asm("add.rn.f32x2 %0, %0, %1;" : "+l"(d) : "l"(a));
}
__device__ __forceinline__ float tanh_ap(float x) {
    float y;
    asm("tanh.approx.f32 %0, %1;" : "=f"(y) : "f"(x));
    return y;
}
__device__ __forceinline__ uint32_t s2u(const void* p) {
    uint32_t a;
    asm("{ .reg .u64 t; cvta.to.shared.u64 t, %1; cvt.u32.u64 %0, t; }"
        : "=r"(a) : "l"(p));
    return a;
}
__device__ __forceinline__ void cp_async16(uint32_t dst, const void* src) {
    asm volatile("cp.async.ca.shared.global [%0], [%1], 16;" :: "r"(dst), "l"(src));
}
__device__ __forceinline__ void cp_commit() {
    asm volatile("cp.async.commit_group;" ::: "memory");
}
template <int N> __device__ __forceinline__ void cp_wait() {
    asm volatile("cp.async.wait_group %0;" :: "n"(N) : "memory");
}
#define BAR96(id) asm volatile("bar.sync %0, %1;" :: "r"(id), "r"(96) : "memory")

__device__ __forceinline__ void mma_tf32(
    float& c0, float& c1, float& c2, float& c3,
    uint32_t a0, uint32_t a1, uint32_t a2, uint32_t a3,
    uint32_t b0, uint32_t b1)
{
    asm volatile(
        "mma.sync.aligned.m16n8k8.row.col.f32.tf32.tf32.f32 "
        "{%0,%1,%2,%3}, {%4,%5,%6,%7}, {%8,%9}, {%0,%1,%2,%3};"
        : "+f"(c0), "+f"(c1), "+f"(c2), "+f"(c3)
        : "r"(a0), "r"(a1), "r"(a2), "r"(a3), "r"(b0), "r"(b1));
}

// ---- fused krec shared layout ---------------------------------------------
struct __align__(16) SMF {
    float pre[48][80];           // pre-gates, permuted [i][q*4+gt]   15360 B
    float Aem[2][48][36];        // embedding k-chunk ring             13824 B
    float Wt[2][32][84];         // W_ih(dir) k-chunk ring             21504 B
    float hist[CHS][20];
    float w1s[20][20];
    float bias_perm[80];
    float hsh[2][24];
    int   tok[48];
};                               // ~54 KB -> 4 blocks/SM

// ---------------------------------------------------------------------------
// krec_fused: 640 blocks x 128 threads, block = (dir, b, chunk).
//  Phase G: warps 0-2 compute pre-gates for the 42-step window via tf32 mma
//    (embeddings + W_ih streamed by all 4 warps through cp.async k-chunks),
//    epilogue written permuted into sm.pre (no global round-trip).
//  Phase R: 3-warp crew recurrence (warm-up + real steps), one bar.sync/step.
//  Phase U: u = hist @ W1dir -> g_uF/g_uB (transposed [s][v][b]).
// ---------------------------------------------------------------------------
__global__ __launch_bounds__(128) void krec_fused(
    const int* __restrict__ x, const float* __restrict__ emb,
    const float* __restrict__ Wif, const float* __restrict__ bfv,
    const float* __restrict__ Wib, const float* __restrict__ bbv,
    const float* __restrict__ Whf, const float* __restrict__ Whb,
    const float* __restrict__ W1g)
{
    extern __shared__ char raw[];
    SMF& sm = *(SMF*)raw;
    const int tid = threadIdx.x;
    const int lane = tid & 31;
    const int w = tid >> 5;
    const int bi = blockIdx.x;
    const int dir = bi / (Bb * NKCH);
    const int rem = bi % (Bb * NKCH);
    const int b = rem / NKCH;
    const int kc = rem % NKCH;
    const float* Wih = dir ? Wib : Wif;
    const float* bia = dir ? bbv : bfv;
    const float* Whh = dir ? Whb : Whf;

    const int c0 = kc * CHS;
    const int re = (c0 + CHS < S) ? (c0 + CHS) : S;
    const int w0 = (c0 - WARM > 0) ? (c0 - WARM) : 0;
    const int ntot = re - w0;
    const int nwarm = c0 - w0;
    const int nreal = re - c0;

    // tokens for window rows (clamped beyond ntot; garbage rows never read)
    if (tid < 48) {
        int ii = (tid < ntot) ? tid : (ntot - 1);
        int it = w0 + ii;
        int s = dir ? (S - 1 - it) : it;
        sm.tok[tid] = (s == 0) ? 2 : ((s == S - 1) ? 3 : x[b * Tt + (s - 1)]);
    }
    if (tid < 80) {
        int q = tid >> 2, gt = tid & 3;
        sm.bias_perm[tid] = bia[gt * 20 + q];
    }
    for (int i = tid; i < 400; i += 128)
        sm.w1s[i / 20][i % 20] = W1g[(dir * 20 + i / 20) * 20 + (i % 20)];
    if (tid < 48) ((float*)sm.hsh)[tid] = 0.f;
    __syncthreads();   // tok visible before cp.async uses it

    // ---- Phase G: windowed GEMM via tf32 mma -------------------------------
    auto issue = [&](int kcc, int bfr) {
        // A: 48 rows x 32 k = 384 float4, 3/thread
#pragma unroll
        for (int i = 0; i < 3; i++) {
            int f = tid + i * 128;
            int r = f >> 3, k4 = f & 7;
            cp_async16(s2u(&sm.Aem[bfr][r][k4 * 4]),
                       emb + (size_t)sm.tok[r] * 128 + kcc * 32 + k4 * 4);
        }
        // W: 32 k x 80 cols = 640 float4, 5/thread
#pragma unroll
        for (int i = 0; i < 5; i++) {
            int f = tid + i * 128;
            int kk = f / 20, c4 = (f % 20) * 4;
            cp_async16(s2u(&sm.Wt[bfr][kk][c4]),
                       Wih + (size_t)(kcc * 32 + kk) * 80 + c4);
        }
        cp_commit();
    };

    issue(0, 0);

    float c[10][4];
#pragma unroll
    for (int t = 0; t < 10; t++)
#pragma unroll
        for (int j = 0; j < 4; j++) c[t][j] = 0.f;

    const int g = lane >> 2, tg = lane & 3;
    const int r0 = w * 16;            // warps 0..2 -> m-tiles

    for (int kcc = 0; kcc < 4; kcc++) {
        const int bfr = kcc & 1;
        if (kcc < 3) { issue(kcc + 1, bfr ^ 1); cp_wait<1>(); }
        else         { cp_wait<0>(); }
        __syncthreads();

        if (w < 3) {
#pragma unroll
            for (int ks = 0; ks < 4; ks++) {
                const int ka = ks * 8 + tg;
                const int ra = r0 + g;
                uint32_t a0 = __float_as_uint(sm.Aem[bfr][ra][ka]);
                uint32_t a1 = __float_as_uint(sm.Aem[bfr][ra + 8][ka]);
                uint32_t a2 = __float_as_uint(sm.Aem[bfr][ra][ka + 4]);
                uint32_t a3 = __float_as_uint(sm.Aem[bfr][ra + 8][ka + 4]);
#pragma unroll
                for (int t = 0; t < 10; t++) {
                    const int nb = t * 8 + g;
                    uint32_t b0 = __float_as_uint(sm.Wt[bfr][ka][nb]);
                    uint32_t b1 = __float_as_uint(sm.Wt[bfr][ka + 4][nb]);
                    mma_tf32(c[t][0], c[t][1], c[t][2], c[t][3],
                             a0, a1, a2, a3, b0, b1);
                }
            }
        }
        __syncthreads();
    }

    // epilogue: permuted store into sm.pre (+bias). col cc -> (cc%20)*4+cc/20
    if (w < 3) {
        const int ra = r0 + g;
#pragma unroll
        for (int t = 0; t < 10; t++) {
            const int cA = t * 8 + 2 * tg;
            const int cB = cA + 1;
            const int sA = (cA % 20) * 4 + cA / 20;
            const int sB = (cB % 20) * 4 + cB / 20;
            sm.pre[ra][sA]     = c[t][0] + sm.bias_perm[sA];
            sm.pre[ra][sB]     = c[t][1] + sm.bias_perm[sB];
            sm.pre[ra + 8][sA] = c[t][2] + sm.bias_perm[sA];
            sm.pre[ra + 8][sB] = c[t][3] + sm.bias_perm[sB];
        }
    }

    // crew setup (registers loaded while GEMM epilogue settles)
    const bool isCrew = (tid < 96);
    const bool gact = isCrew && (tid < 80);
    const int ctc = gact ? tid : 76;
    const int q = ctc >> 2, gt = ctc & 3;
    const int gcl = gt * 20 + q;
    const int cb = lane & ~3;
    const float szc = (gt == 2) ? 1.f : 0.5f;
    const float aac = (gt == 2) ? 1.f : 0.5f;
    const float bbc = (gt == 2) ? 0.f : 0.5f;
    const bool isG0 = gact && (gt == 0);
    ull wk[10];
    float creg = 0.f;
    if (isCrew) {
#pragma unroll
        for (int j = 0; j < 10; j++)
            wk[j] = pk2(Whh[(2 * j) * 80 + gcl], Whh[(2 * j + 1) * 80 + gcl]);
    }
    __syncthreads();   // pre[] complete

    // ---- Phase R: recurrence ----------------------------------------------
    if (isCrew) {
        float prez = sm.pre[0][ctc];
        for (int i = 0; i < ntot; i++) {
            const int par = i & 1;
            const ulonglong2* hp = (const ulonglong2*)sm.hsh[par];
            ulonglong2 h0 = hp[0], h1 = hp[1], h2 = hp[2], h3 = hp[3], h4 = hp[4];
            ull a0 = pk2(prez, 0.f), a1 = 0ull;
            ffma2(a0, h0.x, wk[0]); ffma2(a1, h0.y, wk[1]);
            ffma2(a0, h1.x, wk[2]); ffma2(a1, h1.y, wk[3]);
            ffma2(a0, h2.x, wk[4]); ffma2(a1, h2.y, wk[5]);
            ffma2(a0, h3.x, wk[6]); ffma2(a1, h3.y, wk[7]);
            ffma2(a0, h4.x, wk[8]); ffma2(a1, h4.y, wk[9]);
            fadd2(a0, a1);
            float lo, hi;
            upk2(lo, hi, a0);
            float z = lo + hi;
            float av = fmaf(tanh_ap(szc * z), aac, bbc);
            float af = __shfl_sync(0xffffffffu, av, cb + 1);
            float ag = __shfl_sync(0xffffffffu, av, cb + 2);
            float ao = __shfl_sync(0xffffffffu, av, cb + 3);
            creg = fmaf(af, creg, av * ag);
            float h = ao * tanh_ap(creg);
            if (isG0) {
                sm.hsh[par ^ 1][q] = h;
                if (i >= nwarm) sm.hist[i - nwarm][q] = h;
            }
            int nx = (i + 1 < ntot) ? (i + 1) : i;
            prez = sm.pre[nx][ctc];
            BAR96(1);
        }
    }
    __syncthreads();

    // ---- Phase U: u = hist @ W1dir -> transposed [s][v][b] -----------------
    if (tid < nreal) {
        float hrow[20];
        const float4* hp4 = (const float4*)sm.hist[tid];
#pragma unroll
        for (int i = 0; i < 5; i++) {
            float4 v = hp4[i];
            hrow[4 * i] = v.x; hrow[4 * i + 1] = v.y;
            hrow[4 * i + 2] = v.z; hrow[4 * i + 3] = v.w;
        }
        ull uacc[10];
#pragma unroll
        for (int v = 0; v < 10; v++) uacc[v] = 0ull;
#pragma unroll
        for (int j = 0; j < 20; j++) {
            ull hj = pk2(hrow[j], hrow[j]);
            const ull* wr = (const ull*)sm.w1s[j];
#pragma unroll
            for (int v = 0; v < 10; v++) ffma2(uacc[v], hj, wr[v]);
        }
        int it = c0 + tid;
        int sg = dir ? (S - 1 - it) : it;
        float* ubase = (dir ? g_uB : g_uF) + (size_t)sg * 640 + b;
#pragma unroll
        for (int v = 0; v < 10; v++) {
            float lo, hi;
            upk2(lo, hi, uacc[v]);
            ubase[(2 * v) * 32] = lo;
            ubase[(2 * v + 1) * 32] = hi;
        }
    }
}

// ---------------------------------------------------------------------------
// Emission. 512 blocks (t, l-half) x 128 threads.
// ---------------------------------------------------------------------------
__global__ __launch_bounds__(128) void k3_emis(
    const float* __restrict__ b1, const float* __restrict__ W2,
    const float* __restrict__ b2, float* __restrict__ out)
{
    __shared__ float hids[128][21];
    __shared__ float b1s[20];
    const int tid = threadIdx.x;
    const int lane = tid & 31;
    const int t = blockIdx.x >> 1;
    const int lh = (blockIdx.x & 1) * 4;

    if (tid < 20) b1s[tid] = b1[tid];

    float wa[20], wb[20];
    const bool hasB = (lane < 18);
#pragma unroll
    for (int qq = 0; qq < 20; qq++) {
        wa[qq] = W2[qq * 50 + lane];
        wb[qq] = hasB ? W2[qq * 50 + 32 + lane] : 0.f;
    }
    const float b2a = b2[lane];
    const float b2b = hasB ? b2[32 + lane] : 0.f;
    __syncthreads();

    // Phase A
    {
        const int l = lh + (tid >> 5), b = tid & 31;
        int s0 = t - 7 + l;
        s0 = s0 < 0 ? 0 : s0;
        const float* uFe = g_uF + (size_t)(t + 2) * 640 + b;
        const float* uBe = g_uB + (size_t)(t + 1) * 640 + b;
        const float* uBs = g_uB + (size_t)s0 * 640 + b;
        const float* uFs = g_uF + (size_t)(s0 + 1) * 640 + b;
#pragma unroll
        for (int v = 0; v < 20; v++) {
            float hp = uFe[v * 32] - uBe[v * 32] + uBs[v * 32] - uFs[v * 32] + b1s[v];
            hids[tid][v] = tanh_ap(hp);
        }
    }
    __syncthreads();

    // Phase B
    const int w = tid >> 5;
    for (int rr = 0; rr < 32; rr++) {
        const int row = w * 32 + rr;
        const int l = lh + (row >> 5), b = row & 31;
        const bool valid = (t - 7 + l) >= 0;
        float o1 = b2a, o2 = b2b;
        const float* hv = hids[row];
#pragma unroll
        for (int qq = 0; qq < 20; qq++) {
            float h = hv[qq];
            o1 = fmaf(h, wa[qq], o1);
            o2 = fmaf(h, wb[qq], o2);
        }
        float* op = out + (((size_t)l * 256 + t) * 32 + b) * 50;
        op[lane] = valid ? o1 : NEGV;
        if (hasB) op[32 + lane] = valid ? o2 : NEGV;
    }
}

// ---------------------------------------------------------------------------
extern "C" void kernel_launch(void* const* d_in, const int* in_sizes, int n_in,
                              void* d_out, int out_size)
{
    const int*   x   = (const int*)d_in[0];
    const float* emb = (const float*)d_in[1];
    const float* Wif = (const float*)d_in[2];
    const float* Whf = (const float*)d_in[3];
    const float* bf  = (const float*)d_in[4];
    const float* Wib = (const float*)d_in[5];
    const float* Whb = (const float*)d_in[6];
    const float* bb  = (const float*)d_in[7];
    const float* W1  = (const float*)d_in[8];
    const float* b1  = (const float*)d_in[9];
    const float* W2  = (const float*)d_in[10];
    const float* b2  = (const float*)d_in[11];
    float* out = (float*)d_out;

    static bool attr_set = false;
    if (!attr_set) {
        cudaFuncSetAttribute(krec_fused, cudaFuncAttributeMaxDynamicSharedMemorySize,
                             (int)sizeof(SMF));
        attr_set = true;
    }
    krec_fused<<<2 * Bb * NKCH, 128, sizeof(SMF)>>>(
        x, emb, Wif, bf, Wib, bb, Whf, Whb, W1);
    k3_emis<<<512, 128>>>(b1, W2, b2, out);
}

// round 17
// speedup vs baseline: 1.8650x; 1.8650x over previous
#include <cuda_runtime.h>
#include <cstdint>
#include <cstddef>

#define NEGV -1e30f

constexpr int Bb = 32, Tt = 256, S = 258, Q = 20;
constexpr int ROWS = S * Bb;          // 8256
constexpr int CHS = 26;               // real steps per chunk
constexpr int WARM = 16;              // warm-up steps
constexpr int NKCH = 10;              // chunks per (dir,b)
constexpr int WIN = CHS + WARM;       // 42

// pre-gates (permuted [row][q*4+gt], row = s*32+b)
__device__ float g_pre_f[ROWS * 80];
__device__ float g_pre_b[ROWS * 80];
// u vectors, transposed [s][v][b]
__device__ float g_uF[S * Q * Bb];
__device__ float g_uB[S * Q * Bb];

typedef unsigned long long ull;

// ---- helpers --------------------------------------------------------------
__device__ __forceinline__ ull pk2(float lo, float hi) {
    ull r;
    asm("mov.b64 %0, {%1, %2};" : "=l"(r) : "f"(lo), "f"(hi));
    return r;
}
__device__ __forceinline__ void upk2(float& lo, float& hi, ull v) {
    asm("mov.b64 {%0, %1}, %2;" : "=f"(lo), "=f"(hi) : "l"(v));
}
__device__ __forceinline__ void ffma2(ull& d, ull a, ull b) {
    asm("fma.rn.f32x2 %0, %1, %2, %0;" : "+l"(d) : "l"(a), "l"(b));
}
__device__ __forceinline__ void fadd2(ull& d, ull a) {
    asm("add.rn.f32x2 %0, %0, %1;" : "+l"(d) : "l"(a));
}
__device__ __forceinline__ float tanh_ap(float x) {
    float y;
    asm("tanh.approx.f32 %0, %1;" : "=f"(y) : "f"(x));
    return y;
}
__device__ __forceinline__ uint32_t s2u(const void* p) {
    uint32_t a;
    asm("{ .reg .u64 t; cvta.to.shared.u64 t, %1; cvt.u32.u64 %0, t; }"
        : "=r"(a) : "l"(p));
    return a;
}
__device__ __forceinline__ void cp_async16(uint32_t dst, const void* src) {
    asm volatile("cp.async.ca.shared.global [%0], [%1], 16;" :: "r"(dst), "l"(src));
}
__device__ __forceinline__ void cp_commit() {
    asm volatile("cp.async.commit_group;" ::: "memory");
}
template <int N> __device__ __forceinline__ void cp_wait() {
    asm volatile("cp.async.wait_group %0;" :: "n"(N) : "memory");
}
#define BAR96(id) asm volatile("bar.sync %0, %1;" :: "r"(id), "r"(96) : "memory")

__device__ __forceinline__ void mma_tf32(
    float& c0, float& c1, float& c2, float& c3,
    uint32_t a0, uint32_t a1, uint32_t a2, uint32_t a3,
    uint32_t b0, uint32_t b1)
{
    asm volatile(
        "mma.sync.aligned.m16n8k8.row.col.f32.tf32.tf32.f32 "
        "{%0,%1,%2,%3}, {%4,%5,%6,%7}, {%8,%9}, {%0,%1,%2,%3};"
        : "+f"(c0), "+f"(c1), "+f"(c2), "+f"(c3)
        : "r"(a0), "r"(a1), "r"(a2), "r"(a3), "r"(b0), "r"(b1));
}

// ---------------------------------------------------------------------------
// Kernel 1: embedding gather + X @ [W_ih_f | W_ih_b] via tf32 mma.sync.
// 258 blocks x 256 threads; 32 rows x 160 cols; cp.async double-buffered
// k-chunks of 32; smem-staged permuted epilogue with coalesced stores.
// ---------------------------------------------------------------------------
struct __align__(16) SK1 {
    float A[2][32][40];
    float W[2][32][168];
    float Cst[32][160];
    float bias_perm[160];
    int   tok[32];
};

__global__ __launch_bounds__(256) void k1_mma(
    const int* __restrict__ x, const float* __restrict__ emb,
    const float* __restrict__ Wf, const float* __restrict__ bfv,
    const float* __restrict__ Wb, const float* __restrict__ bbv)
{
    extern __shared__ char raw[];
    SK1& sm = *(SK1*)raw;
    const int tid = threadIdx.x;
    const int lane = tid & 31;
    const int w = tid >> 5;
    const int row0 = blockIdx.x * 32;

    if (tid < 32) {
        int r = row0 + tid;
        int s = r >> 5, b = r & 31;
        sm.tok[tid] = (s == 0) ? 2 : ((s == S - 1) ? 3 : x[b * Tt + (s - 1)]);
    }
    if (tid < 160) {
        int d = tid >= 80;
        int ss = tid - 80 * d;
        int q = ss >> 2, gt = ss & 3;
        sm.bias_perm[tid] = (d ? bbv : bfv)[gt * 20 + q];
    }
    __syncthreads();

    auto issue = [&](int kc, int bfr) {
        {
            int r = tid >> 3, k4 = tid & 7;
            cp_async16(s2u(&sm.A[bfr][r][k4 * 4]),
                       emb + (size_t)sm.tok[r] * 128 + kc * 32 + k4 * 4);
        }
#pragma unroll
        for (int i = 0; i < 5; i++) {
            int f = tid + i * 256;
            int kk = f / 40, c = (f % 40) * 4;
            const float* src = (c < 80)
                ? (Wf + (size_t)(kc * 32 + kk) * 80 + c)
                : (Wb + (size_t)(kc * 32 + kk) * 80 + (c - 80));
            cp_async16(s2u(&sm.W[bfr][kk][c]), src);
        }
        cp_commit();
    };

    issue(0, 0);

    float c[5][4];
#pragma unroll
    for (int t = 0; t < 5; t++)
#pragma unroll
        for (int j = 0; j < 4; j++) c[t][j] = 0.f;

    const int r0 = (w & 1) * 16;
    const int nb0 = (w >> 1) * 40;
    const int g = lane >> 2, tg = lane & 3;

    for (int kc = 0; kc < 4; kc++) {
        const int bfr = kc & 1;
        if (kc < 3) { issue(kc + 1, bfr ^ 1); cp_wait<1>(); }
        else        { cp_wait<0>(); }
        __syncthreads();

#pragma unroll
        for (int ks = 0; ks < 4; ks++) {
            const int ka = ks * 8 + tg;
            const int ra = r0 + g;
            uint32_t a0 = __float_as_uint(sm.A[bfr][ra][ka]);
            uint32_t a1 = __float_as_uint(sm.A[bfr][ra + 8][ka]);
            uint32_t a2 = __float_as_uint(sm.A[bfr][ra][ka + 4]);
            uint32_t a3 = __float_as_uint(sm.A[bfr][ra + 8][ka + 4]);
#pragma unroll
            for (int t = 0; t < 5; t++) {
                const int nb = nb0 + t * 8 + g;
                uint32_t b0 = __float_as_uint(sm.W[bfr][ka][nb]);
                uint32_t b1 = __float_as_uint(sm.W[bfr][ka + 4][nb]);
                mma_tf32(c[t][0], c[t][1], c[t][2], c[t][3],
                         a0, a1, a2, a3, b0, b1);
            }
        }
        __syncthreads();
    }

    auto scol = [](int col) {
        int d = col >= 80;
        int cc = col - 80 * d;
        return d * 80 + (cc % 20) * 4 + cc / 20;
    };
    const int ra = r0 + g;
#pragma unroll
    for (int t = 0; t < 5; t++) {
        const int cA = nb0 + t * 8 + 2 * tg;
        sm.Cst[ra][scol(cA)]     = c[t][0];
        sm.Cst[ra][scol(cA + 1)] = c[t][1];
        sm.Cst[ra + 8][scol(cA)]     = c[t][2];
        sm.Cst[ra + 8][scol(cA + 1)] = c[t][3];
    }
    __syncthreads();

#pragma unroll
    for (int i = 0; i < 5; i++) {
        int f = tid + i * 256;
        int r = f / 40, j = f % 40;
        float4 v = *(const float4*)&sm.Cst[r][j * 4];
        float4 bv = *(const float4*)&sm.bias_perm[j * 4];
        v.x += bv.x; v.y += bv.y; v.z += bv.z; v.w += bv.w;
        float* dst = (j < 20)
            ? (g_pre_f + (size_t)(row0 + r) * 80 + j * 4)
            : (g_pre_b + (size_t)(row0 + r) * 80 + (j - 20) * 4);
        *(float4*)dst = v;
    }
}

// ---------------------------------------------------------------------------
// krec: chunked LSTM recurrence with warm-up. 640 blocks x 128 threads.
// 3-warp crew (lane ct = cell*4+gate, shfl cell update, one bar/step).
// ---------------------------------------------------------------------------
struct __align__(16) SMR {
    float pre[WIN][80];
    float hist[CHS][20];
    float w1s[20][20];
    float hsh[2][24];
};

__global__ __launch_bounds__(128) void krec(
    const float* __restrict__ Whf, const float* __restrict__ Whb,
    const float* __restrict__ W1g)
{
    __shared__ SMR sm;
    const int tid = threadIdx.x;
    const int bi = blockIdx.x;
    const int dir = bi / (Bb * NKCH);
    const int rem = bi % (Bb * NKCH);
    const int b = rem / NKCH;
    const int kc = rem % NKCH;
    const float* Whh = dir ? Whb : Whf;

    const int c0 = kc * CHS;
    const int re = (c0 + CHS < S) ? (c0 + CHS) : S;
    const int w0 = (c0 - WARM > 0) ? (c0 - WARM) : 0;
    const int ntot = re - w0;
    const int nwarm = c0 - w0;
    const int nreal = re - c0;

    const float* gpre = dir ? g_pre_b : g_pre_f;
    for (int f = tid; f < ntot * 20; f += 128) {
        int i = f / 20, j = f % 20;
        int it = w0 + i;
        int sg = dir ? (S - 1 - it) : it;
        cp_async16(s2u(&sm.pre[i][j * 4]), gpre + ((size_t)sg * 32 + b) * 80 + j * 4);
    }
    cp_commit();

    for (int i = tid; i < 400; i += 128)
        sm.w1s[i / 20][i % 20] = W1g[(dir * 20 + i / 20) * 20 + (i % 20)];

    const int lane = tid & 31;
    const bool isCrew = (tid < 96);
    const bool gact = isCrew && (tid < 80);
    const int ctc = gact ? tid : 76;
    const int q = ctc >> 2, gt = ctc & 3;
    const int gcl = gt * 20 + q;
    const int cb = lane & ~3;
    const float szc = (gt == 2) ? 1.f : 0.5f;
    const float aac = (gt == 2) ? 1.f : 0.5f;
    const float bbc = (gt == 2) ? 0.f : 0.5f;
    const bool isG0 = gact && (gt == 0);
    ull wk[10];
    float creg = 0.f;
    if (isCrew) {
#pragma unroll
        for (int j = 0; j < 10; j++)
            wk[j] = pk2(Whh[(2 * j) * 80 + gcl], Whh[(2 * j + 1) * 80 + gcl]);
        if (tid < 48) ((float*)sm.hsh)[tid] = 0.f;
    }
    cp_wait<0>();
    __syncthreads();

    if (isCrew) {
        float prez = sm.pre[0][ctc];
        for (int i = 0; i < ntot; i++) {
            const int par = i & 1;
            const ulonglong2* hp = (const ulonglong2*)sm.hsh[par];
            ulonglong2 h0 = hp[0], h1 = hp[1], h2 = hp[2], h3 = hp[3], h4 = hp[4];
            ull a0 = pk2(prez, 0.f), a1 = 0ull;
            ffma2(a0, h0.x, wk[0]); ffma2(a1, h0.y, wk[1]);
            ffma2(a0, h1.x, wk[2]); ffma2(a1, h1.y, wk[3]);
            ffma2(a0, h2.x, wk[4]); ffma2(a1, h2.y, wk[5]);
            ffma2(a0, h3.x, wk[6]); ffma2(a1, h3.y, wk[7]);
            ffma2(a0, h4.x, wk[8]); ffma2(a1, h4.y, wk[9]);
            fadd2(a0, a1);
            float lo, hi;
            upk2(lo, hi, a0);
            float z = lo + hi;
            float av = fmaf(tanh_ap(szc * z), aac, bbc);
            float af = __shfl_sync(0xffffffffu, av, cb + 1);
            float ag = __shfl_sync(0xffffffffu, av, cb + 2);
            float ao = __shfl_sync(0xffffffffu, av, cb + 3);
            creg = fmaf(af, creg, av * ag);
            float h = ao * tanh_ap(creg);
            if (isG0) {
                sm.hsh[par ^ 1][q] = h;
                if (i >= nwarm) sm.hist[i - nwarm][q] = h;
            }
            int nx = (i + 1 < ntot) ? (i + 1) : i;
            prez = sm.pre[nx][ctc];
            BAR96(1);
        }
    }
    __syncthreads();

    if (tid < nreal) {
        float hrow[20];
        const float4* hp4 = (const float4*)sm.hist[tid];
#pragma unroll
        for (int i = 0; i < 5; i++) {
            float4 v = hp4[i];
            hrow[4 * i] = v.x; hrow[4 * i + 1] = v.y;
            hrow[4 * i + 2] = v.z; hrow[4 * i + 3] = v.w;
        }
        ull uacc[10];
#pragma unroll
        for (int v = 0; v < 10; v++) uacc[v] = 0ull;
#pragma unroll
        for (int j = 0; j < 20; j++) {
            ull hj = pk2(hrow[j], hrow[j]);
            const ull* wr = (const ull*)sm.w1s[j];
#pragma unroll
            for (int v = 0; v < 10; v++) ffma2(uacc[v], hj, wr[v]);
        }
        int it = c0 + tid;
        int sg = dir ? (S - 1 - it) : it;
        float* ubase = (dir ? g_uB : g_uF) + (size_t)sg * 640 + b;
#pragma unroll
        for (int v = 0; v < 10; v++) {
            float lo, hi;
            upk2(lo, hi, uacc[v]);
            ubase[(2 * v) * 32] = lo;
            ubase[(2 * v + 1) * 32] = hi;
        }
    }
}

// ---------------------------------------------------------------------------
// Emission. 1024 blocks (t, l-quarter of 2 l-values = 64 rows) x 128 thr.
//  Phase A: tid&63 = row, tid>>6 = v-half: hid into smem (coalesced u loads).
//  Phase B: warp = 16 rows; lane = col pair (o_lane, o_32+lane) as ONE f32x2
//           accumulator; hv loaded via 5 broadcast LDS.128; 20 FFMA2/row.
// ---------------------------------------------------------------------------
__global__ __launch_bounds__(128) void k3_emis(
    const float* __restrict__ b1, const float* __restrict__ W2,
    const float* __restrict__ b2, float* __restrict__ out)
{
    __shared__ __align__(16) float hids[64][20];
    __shared__ float b1s[20];
    const int tid = threadIdx.x;
    const int lane = tid & 31;
    const int t = blockIdx.x >> 2;
    const int lh = (blockIdx.x & 3) * 2;     // first of 2 l values

    if (tid < 20) b1s[tid] = b1[tid];

    // W2 col pair (lane, 32+lane) packed as f32x2
    ull wpk[20];
    const bool hasB = (lane < 18);
#pragma unroll
    for (int qq = 0; qq < 20; qq++) {
        float wa = W2[qq * 50 + lane];
        float wb = hasB ? W2[qq * 50 + 32 + lane] : 0.f;
        wpk[qq] = pk2(wa, wb);
    }
    const ull bpk = pk2(b2[lane], hasB ? b2[32 + lane] : 0.f);
    __syncthreads();

    // Phase A: 64 rows x 2 v-halves
    {
        const int row = tid & 63;
        const int vh = (tid >> 6) * 10;
        const int l = lh + (row >> 5), b = row & 31;
        int s0 = t - 7 + l;
        s0 = s0 < 0 ? 0 : s0;
        const float* uFe = g_uF + (size_t)(t + 2) * 640 + b;
        const float* uBe = g_uB + (size_t)(t + 1) * 640 + b;
        const float* uBs = g_uB + (size_t)s0 * 640 + b;
        const float* uFs = g_uF + (size_t)(s0 + 1) * 640 + b;
#pragma unroll
        for (int v = vh; v < vh + 10; v++) {
            float hp = uFe[v * 32] - uBe[v * 32] + uBs[v * 32] - uFs[v * 32] + b1s[v];
            hids[row][v] = tanh_ap(hp);
        }
    }
    __syncthreads();

    // Phase B: warp w handles rows [w*16, w*16+16)
    const int w = tid >> 5;
#pragma unroll 2
    for (int rr = 0; rr < 16; rr++) {
        const int row = w * 16 + rr;
        const int l = lh + (row >> 5), b = row & 31;
        const bool valid = (t - 7 + l) >= 0;
        const float4* hp4 = (const float4*)hids[row];
        float4 v0 = hp4[0], v1 = hp4[1], v2 = hp4[2], v3 = hp4[3], v4 = hp4[4];
        float hv[20] = {v0.x, v0.y, v0.z, v0.w, v1.x, v1.y, v1.z, v1.w,
                        v2.x, v2.y, v2.z, v2.w, v3.x, v3.y, v3.z, v3.w,
                        v4.x, v4.y, v4.z, v4.w};
        ull acc = bpk;
#pragma unroll
        for (int qq = 0; qq < 20; qq++) ffma2(acc, pk2(hv[qq], hv[qq]), wpk[qq]);
        float o1, o2;
        upk2(o1, o2, acc);
        float* op = out + (((size_t)l * 256 + t) * 32 + b) * 50;
        op[lane] = valid ? o1 : NEGV;
        if (hasB) op[32 + lane] = valid ? o2 : NEGV;
    }
}

// ---------------------------------------------------------------------------
extern "C" void kernel_launch(void* const* d_in, const int* in_sizes, int n_in,
                              void* d_out, int out_size)
{
    const int*   x   = (const int*)d_in[0];
    const float* emb = (const float*)d_in[1];
    const float* Wif = (const float*)d_in[2];
    const float* Whf = (const float*)d_in[3];
    const float* bf  = (const float*)d_in[4];
    const float* Wib = (const float*)d_in[5];
    const float* Whb = (const float*)d_in[6];
    const float* bb  = (const float*)d_in[7];
    const float* W1  = (const float*)d_in[8];
    const float* b1  = (const float*)d_in[9];
    const float* W2  = (const float*)d_in[10];
    const float* b2  = (const float*)d_in[11];
    float* out = (float*)d_out;

    static bool attr_set = false;
    if (!attr_set) {
        cudaFuncSetAttribute(k1_mma, cudaFuncAttributeMaxDynamicSharedMemorySize,
                             (int)sizeof(SK1));
        attr_set = true;
    }
    k1_mma<<<258, 256, sizeof(SK1)>>>(x, emb, Wif, bf, Wib, bb);
    krec<<<2 * Bb * NKCH, 128>>>(Whf, Whb, W1);
    k3_emis<<<1024, 128>>>(b1, W2, b2, out);
}